// round 1
// baseline (speedup 1.0000x reference)
#include <cuda_runtime.h>
#include <cuda_bf16.h>
#include <cstdint>

// ---------------------------------------------------------------------------
// Conv3DNorm: x[8,128,32,32,32] (*) w[128,128,3,3,3] (pad=1), styles==1 so the
// modulation collapses to a per-cout demod scale. Epilogue: +bias, lrelu(0.2),
// *sqrt(2), clamp +-256.
//
// Kernel 1 (prep): d[co] = rsqrt(sum w^2 + 1e-8); write w*d to g_wbuf in
//                  [ci][k][co] layout (co contiguous -> f32x2-friendly).
// Kernel 2 (conv): direct conv, packed f32x2 accumulators over cout pairs.
// ---------------------------------------------------------------------------

#define CIN   128
#define COUT  128
#define DIMZ  32
#define DIMY  32
#define DIMX  32
#define KVOL  27
#define CI_CHUNK 4

// demodulated, transposed weights: [ci*27+k][co]
__device__ float g_wbuf[CIN * KVOL * COUT];

// ---------------- packed f32x2 helpers ----------------
__device__ __forceinline__ unsigned long long pk2(float lo, float hi) {
    unsigned long long r;
    asm("mov.b64 %0, {%1, %2};" : "=l"(r) : "f"(lo), "f"(hi));
    return r;
}
__device__ __forceinline__ void upk2(unsigned long long v, float& lo, float& hi) {
    asm("mov.b64 {%0, %1}, %2;" : "=f"(lo), "=f"(hi) : "l"(v));
}
__device__ __forceinline__ void fma2(unsigned long long& d,
                                     unsigned long long a,
                                     unsigned long long b) {
    // d = a*b + d (2-way SIMD fp32)
    asm("fma.rn.f32x2 %0, %1, %2, %0;" : "+l"(d) : "l"(a), "l"(b));
}

// ---------------------------------------------------------------------------
// prep: one block per cout. Reduce sum of squares, scale, write transposed.
// ---------------------------------------------------------------------------
__global__ void prep_kernel(const float* __restrict__ w) {
    const int co  = blockIdx.x;
    const int tid = threadIdx.x;
    const int CK  = CIN * KVOL;  // 3456

    float s = 0.0f;
    const float* wc = w + (size_t)co * CK;
    for (int i = tid; i < CK; i += 256) {
        float v = wc[i];
        s += v * v;
    }
    __shared__ float red[256];
    red[tid] = s;
    __syncthreads();
    for (int off = 128; off > 0; off >>= 1) {
        if (tid < off) red[tid] += red[tid + off];
        __syncthreads();
    }
    const float d = rsqrtf(red[0] + 1e-8f);

    for (int i = tid; i < CK; i += 256) {
        g_wbuf[(size_t)i * COUT + co] = wc[i] * d;
    }
}

// ---------------------------------------------------------------------------
// conv: grid = (8 ytiles, 32 z, 8 b * 2 cohalf), block = 128 threads.
// Block computes out[b, co_block..co_block+63, z, y0..y0+3, 0..31].
// Thread (tx = lane x, g = co-group of 16 couts = 8 f32x2 pairs).
// ---------------------------------------------------------------------------
__global__ __launch_bounds__(128)
void conv_kernel(const float* __restrict__ x,
                 const float* __restrict__ bias,
                 float* __restrict__ out) {
    const int tid = threadIdx.x;
    const int tx  = tid & 31;     // x position
    const int g   = tid >> 5;     // co-group: 16 couts

    const int y0       = blockIdx.x * 4;
    const int z        = blockIdx.y;
    const int b        = blockIdx.z >> 1;
    const int co_block = (blockIdx.z & 1) * 64;

    __shared__ float sx[CI_CHUNK][3][6][36];   // [ci][dz][yrow][x(+halo,pad)]
    __shared__ float sw[CI_CHUNK][KVOL][64];   // [ci][k][co]

    unsigned long long acc[8][4];
    #pragma unroll
    for (int cp = 0; cp < 8; cp++)
        #pragma unroll
        for (int y = 0; y < 4; y++) acc[cp][y] = 0ull;

    const float* xb = x + (size_t)b * CIN * (DIMZ * DIMY * DIMX);

    for (int ci0 = 0; ci0 < CIN; ci0 += CI_CHUNK) {
        __syncthreads();

        // ---- stage x tile (with zero halo) ----
        for (int idx = tid; idx < CI_CHUNK * 3 * 6 * 36; idx += 128) {
            int xx = idx % 36;
            int t  = idx / 36;
            int yy = t % 6; t /= 6;
            int dz = t % 3;
            int ci = t / 3;
            int gx = xx - 1;
            int gy = y0 - 1 + yy;
            int gz = z - 1 + dz;
            float v = 0.0f;
            if ((unsigned)gx < (unsigned)DIMX &&
                (unsigned)gy < (unsigned)DIMY &&
                (unsigned)gz < (unsigned)DIMZ) {
                v = xb[(size_t)(ci0 + ci) * (DIMZ * DIMY * DIMX)
                       + gz * (DIMY * DIMX) + gy * DIMX + gx];
            }
            ((float*)sx)[idx] = v;
        }

        // ---- stage w tile (float4) ----
        for (int idx = tid; idx < CI_CHUNK * KVOL * 16; idx += 128) {
            int c4 = idx % 16;
            int t  = idx / 16;
            int k  = t % KVOL;
            int ci = t / KVOL;
            float4 v = *(const float4*)&g_wbuf[((size_t)(ci0 + ci) * KVOL + k) * COUT
                                               + co_block + c4 * 4];
            *(float4*)&sw[ci][k][c4 * 4] = v;
        }
        __syncthreads();

        // ---- compute ----
        for (int ci = 0; ci < CI_CHUNK; ci++) {
            for (int dz = 0; dz < 3; dz++) {
                for (int dy = 0; dy < 3; dy++) {
                    // x values for 4 output rows x 3 dx taps, duplicated-packed
                    unsigned long long xv[4][3];
                    #pragma unroll
                    for (int y = 0; y < 4; y++) {
                        const float* row = &sx[ci][dz][y + dy][tx];
                        float a = row[0], bb = row[1], c = row[2];
                        xv[y][0] = pk2(a, a);
                        xv[y][1] = pk2(bb, bb);
                        xv[y][2] = pk2(c, c);
                    }
                    const int kbase = (dz * 3 + dy) * 3;
                    #pragma unroll
                    for (int dx = 0; dx < 3; dx++) {
                        const unsigned long long* wrow =
                            (const unsigned long long*)&sw[ci][kbase + dx][g * 16];
                        unsigned long long wv[8];
                        #pragma unroll
                        for (int cp = 0; cp < 4; cp++) {
                            ulonglong2 ww = ((const ulonglong2*)wrow)[cp];
                            wv[2 * cp]     = ww.x;
                            wv[2 * cp + 1] = ww.y;
                        }
                        #pragma unroll
                        for (int cp = 0; cp < 8; cp++)
                            #pragma unroll
                            for (int y = 0; y < 4; y++)
                                fma2(acc[cp][y], wv[cp], xv[y][dx]);
                    }
                }
            }
        }
    }

    // ---- epilogue: +bias, lrelu(0.2), *sqrt(2), clamp +-256 ----
    const float SQ2 = 1.41421356237309515f;
    #pragma unroll
    for (int cp = 0; cp < 8; cp++) {
        const int co0 = co_block + g * 16 + 2 * cp;
        const float b0 = bias[co0];
        const float b1 = bias[co0 + 1];
        #pragma unroll
        for (int y = 0; y < 4; y++) {
            float lo, hi;
            upk2(acc[cp][y], lo, hi);
            float v0 = lo + b0;
            float v1 = hi + b1;
            v0 = (v0 > 0.0f) ? v0 : 0.2f * v0;
            v1 = (v1 > 0.0f) ? v1 : 0.2f * v1;
            v0 = fminf(fmaxf(v0 * SQ2, -256.0f), 256.0f);
            v1 = fminf(fmaxf(v1 * SQ2, -256.0f), 256.0f);
            const size_t sp = (size_t)z * (DIMY * DIMX) + (y0 + y) * DIMX + tx;
            out[((size_t)b * COUT + co0) * (DIMZ * DIMY * DIMX) + sp]       = v0;
            out[((size_t)b * COUT + co0 + 1) * (DIMZ * DIMY * DIMX) + sp]   = v1;
        }
    }
}

// ---------------------------------------------------------------------------
extern "C" void kernel_launch(void* const* d_in, const int* in_sizes, int n_in,
                              void* d_out, int out_size) {
    const float* x    = (const float*)d_in[0];   // [8,128,32,32,32]
    const float* w    = (const float*)d_in[1];   // [128,128,3,3,3]
    const float* bias = (const float*)d_in[2];   // [128]
    float* out        = (float*)d_out;

    prep_kernel<<<COUT, 256>>>(w);

    dim3 grid(8 /*ytiles*/, DIMZ /*z*/, 8 * 2 /*b * cohalf*/);
    conv_kernel<<<grid, 128>>>(x, bias, out);
}

// round 2
// speedup vs baseline: 1.0017x; 1.0017x over previous
#include <cuda_runtime.h>
#include <cuda_bf16.h>
#include <cstdint>

// ---------------------------------------------------------------------------
// Conv3DNorm: x[8,128,32,32,32] (*) w[128,128,3,3,3] (pad=1), styles==1 so the
// modulation collapses to a per-cout demod scale. Epilogue: +bias, lrelu(0.2),
// *sqrt(2), clamp +-256.
//
// Kernel 1 (prep): d[co] = rsqrt(sum w^2 + 1e-8); write w*d to g_wbuf in
//                  [ci][k][co] layout (co contiguous -> f32x2-friendly).
// Kernel 2 (conv): direct conv, packed f32x2 accumulators over cout pairs.
// ---------------------------------------------------------------------------

#define CIN   128
#define COUT  128
#define DIMZ  32
#define DIMY  32
#define DIMX  32
#define KVOL  27
#define CI_CHUNK 4

// demodulated, transposed weights: [ci*27+k][co]
__device__ float g_wbuf[CIN * KVOL * COUT];

// ---------------- packed f32x2 helpers ----------------
__device__ __forceinline__ unsigned long long pk2(float lo, float hi) {
    unsigned long long r;
    asm("mov.b64 %0, {%1, %2};" : "=l"(r) : "f"(lo), "f"(hi));
    return r;
}
__device__ __forceinline__ void upk2(unsigned long long v, float& lo, float& hi) {
    asm("mov.b64 {%0, %1}, %2;" : "=f"(lo), "=f"(hi) : "l"(v));
}
__device__ __forceinline__ void fma2(unsigned long long& d,
                                     unsigned long long a,
                                     unsigned long long b) {
    // d = a*b + d (2-way SIMD fp32)
    asm("fma.rn.f32x2 %0, %1, %2, %0;" : "+l"(d) : "l"(a), "l"(b));
}

// ---------------------------------------------------------------------------
// prep: one block per cout. Reduce sum of squares, scale, write transposed.
// ---------------------------------------------------------------------------
__global__ void prep_kernel(const float* __restrict__ w) {
    const int co  = blockIdx.x;
    const int tid = threadIdx.x;
    const int CK  = CIN * KVOL;  // 3456

    float s = 0.0f;
    const float* wc = w + (size_t)co * CK;
    for (int i = tid; i < CK; i += 256) {
        float v = wc[i];
        s += v * v;
    }
    __shared__ float red[256];
    red[tid] = s;
    __syncthreads();
    for (int off = 128; off > 0; off >>= 1) {
        if (tid < off) red[tid] += red[tid + off];
        __syncthreads();
    }
    const float d = rsqrtf(red[0] + 1e-8f);

    for (int i = tid; i < CK; i += 256) {
        g_wbuf[(size_t)i * COUT + co] = wc[i] * d;
    }
}

// ---------------------------------------------------------------------------
// conv: grid = (8 ytiles, 32 z, 8 b * 2 cohalf), block = 128 threads.
// Block computes out[b, co_block..co_block+63, z, y0..y0+3, 0..31].
// Thread (tx = lane x, g = co-group of 16 couts = 8 f32x2 pairs).
// ---------------------------------------------------------------------------
__global__ __launch_bounds__(128)
void conv_kernel(const float* __restrict__ x,
                 const float* __restrict__ bias,
                 float* __restrict__ out) {
    const int tid = threadIdx.x;
    const int tx  = tid & 31;     // x position
    const int g   = tid >> 5;     // co-group: 16 couts

    const int y0       = blockIdx.x * 4;
    const int z        = blockIdx.y;
    const int b        = blockIdx.z >> 1;
    const int co_block = (blockIdx.z & 1) * 64;

    __shared__ float sx[CI_CHUNK][3][6][36];   // [ci][dz][yrow][x(+halo,pad)]
    __shared__ float sw[CI_CHUNK][KVOL][64];   // [ci][k][co]

    unsigned long long acc[8][4];
    #pragma unroll
    for (int cp = 0; cp < 8; cp++)
        #pragma unroll
        for (int y = 0; y < 4; y++) acc[cp][y] = 0ull;

    const float* xb = x + (size_t)b * CIN * (DIMZ * DIMY * DIMX);

    for (int ci0 = 0; ci0 < CIN; ci0 += CI_CHUNK) {
        __syncthreads();

        // ---- stage x tile (with zero halo) ----
        for (int idx = tid; idx < CI_CHUNK * 3 * 6 * 36; idx += 128) {
            int xx = idx % 36;
            int t  = idx / 36;
            int yy = t % 6; t /= 6;
            int dz = t % 3;
            int ci = t / 3;
            int gx = xx - 1;
            int gy = y0 - 1 + yy;
            int gz = z - 1 + dz;
            float v = 0.0f;
            if ((unsigned)gx < (unsigned)DIMX &&
                (unsigned)gy < (unsigned)DIMY &&
                (unsigned)gz < (unsigned)DIMZ) {
                v = xb[(size_t)(ci0 + ci) * (DIMZ * DIMY * DIMX)
                       + gz * (DIMY * DIMX) + gy * DIMX + gx];
            }
            ((float*)sx)[idx] = v;
        }

        // ---- stage w tile (float4) ----
        for (int idx = tid; idx < CI_CHUNK * KVOL * 16; idx += 128) {
            int c4 = idx % 16;
            int t  = idx / 16;
            int k  = t % KVOL;
            int ci = t / KVOL;
            float4 v = *(const float4*)&g_wbuf[((size_t)(ci0 + ci) * KVOL + k) * COUT
                                               + co_block + c4 * 4];
            *(float4*)&sw[ci][k][c4 * 4] = v;
        }
        __syncthreads();

        // ---- compute ----
        for (int ci = 0; ci < CI_CHUNK; ci++) {
            for (int dz = 0; dz < 3; dz++) {
                for (int dy = 0; dy < 3; dy++) {
                    // x values for 4 output rows x 3 dx taps, duplicated-packed
                    unsigned long long xv[4][3];
                    #pragma unroll
                    for (int y = 0; y < 4; y++) {
                        const float* row = &sx[ci][dz][y + dy][tx];
                        float a = row[0], bb = row[1], c = row[2];
                        xv[y][0] = pk2(a, a);
                        xv[y][1] = pk2(bb, bb);
                        xv[y][2] = pk2(c, c);
                    }
                    const int kbase = (dz * 3 + dy) * 3;
                    #pragma unroll
                    for (int dx = 0; dx < 3; dx++) {
                        const unsigned long long* wrow =
                            (const unsigned long long*)&sw[ci][kbase + dx][g * 16];
                        unsigned long long wv[8];
                        #pragma unroll
                        for (int cp = 0; cp < 4; cp++) {
                            ulonglong2 ww = ((const ulonglong2*)wrow)[cp];
                            wv[2 * cp]     = ww.x;
                            wv[2 * cp + 1] = ww.y;
                        }
                        #pragma unroll
                        for (int cp = 0; cp < 8; cp++)
                            #pragma unroll
                            for (int y = 0; y < 4; y++)
                                fma2(acc[cp][y], wv[cp], xv[y][dx]);
                    }
                }
            }
        }
    }

    // ---- epilogue: +bias, lrelu(0.2), *sqrt(2), clamp +-256 ----
    const float SQ2 = 1.41421356237309515f;
    #pragma unroll
    for (int cp = 0; cp < 8; cp++) {
        const int co0 = co_block + g * 16 + 2 * cp;
        const float b0 = bias[co0];
        const float b1 = bias[co0 + 1];
        #pragma unroll
        for (int y = 0; y < 4; y++) {
            float lo, hi;
            upk2(acc[cp][y], lo, hi);
            float v0 = lo + b0;
            float v1 = hi + b1;
            v0 = (v0 > 0.0f) ? v0 : 0.2f * v0;
            v1 = (v1 > 0.0f) ? v1 : 0.2f * v1;
            v0 = fminf(fmaxf(v0 * SQ2, -256.0f), 256.0f);
            v1 = fminf(fmaxf(v1 * SQ2, -256.0f), 256.0f);
            const size_t sp = (size_t)z * (DIMY * DIMX) + (y0 + y) * DIMX + tx;
            out[((size_t)b * COUT + co0) * (DIMZ * DIMY * DIMX) + sp]       = v0;
            out[((size_t)b * COUT + co0 + 1) * (DIMZ * DIMY * DIMX) + sp]   = v1;
        }
    }
}

// ---------------------------------------------------------------------------
extern "C" void kernel_launch(void* const* d_in, const int* in_sizes, int n_in,
                              void* d_out, int out_size) {
    const float* x    = (const float*)d_in[0];   // [8,128,32,32,32]
    const float* w    = (const float*)d_in[1];   // [128,128,3,3,3]
    const float* bias = (const float*)d_in[2];   // [128]
    float* out        = (float*)d_out;

    prep_kernel<<<COUT, 256>>>(w);

    dim3 grid(8 /*ytiles*/, DIMZ /*z*/, 8 * 2 /*b * cohalf*/);
    conv_kernel<<<grid, 128>>>(x, bias, out);
}

// round 8
// speedup vs baseline: 3.3083x; 3.3026x over previous
#include <cuda_runtime.h>
#include <cuda_bf16.h>
#include <cstdint>

// ===========================================================================
// Conv3DNorm via implicit GEMM on warp-level tf32 mma.sync (m16n8k8).
// styles==1 -> demod collapses to per-cout scale. Epilogue: +bias, lrelu(0.2),
// *sqrt(2), clamp +-256.
//
// Per CTA: D[128 co, 256 n], n = 8 y-rows x 32 x at fixed (b, z).
// K = tap-major: k8 block = 8 consecutive ci at one of the 27 taps.
// B = ext spatial tile in smem (taps = address offsets), tf32-converted.
// A = demod weights pre-packed in mma fragment order (LDG.128 per frag).
// ===========================================================================

// A pack: [tap 27][ciblk 16][mblk 8][lane 32][reg 4]  (tf32 bits), 1.77 MB
__device__ uint32_t g_wA[27 * 16 * 8 * 32 * 4];

__device__ __forceinline__ uint32_t f2tf32(float v) {
    uint32_t r;
    asm("cvt.rna.tf32.f32 %0, %1;" : "=r"(r) : "f"(v));
    return r;
}

__device__ __forceinline__ void mma8(float* d, uint4 a, uint32_t b0, uint32_t b1) {
    asm volatile(
        "mma.sync.aligned.m16n8k8.row.col.f32.tf32.tf32.f32 "
        "{%0,%1,%2,%3}, {%4,%5,%6,%7}, {%8,%9}, {%0,%1,%2,%3};"
        : "+f"(d[0]), "+f"(d[1]), "+f"(d[2]), "+f"(d[3])
        : "r"(a.x), "r"(a.y), "r"(a.z), "r"(a.w), "r"(b0), "r"(b1));
}

// ---------------------------------------------------------------------------
// prep: demodulate + tf32-convert + pack into fragment order.
// fragment map (m16n8k8): reg r: row = (lane>>2) + 8*(r&1),
//                                 col(k) = (lane&3) + 4*(r>>1)
// ---------------------------------------------------------------------------
__global__ void prep_kernel(const float* __restrict__ w) {
    const int co = blockIdx.x, tid = threadIdx.x;  // 128 x 128
    const float* wc = w + co * 3456;
    float s = 0.f;
    for (int i = tid; i < 3456; i += 128) { float v = wc[i]; s += v * v; }
    #pragma unroll
    for (int o = 16; o; o >>= 1) s += __shfl_xor_sync(~0u, s, o);
    __shared__ float red[4];
    if ((tid & 31) == 0) red[tid >> 5] = s;
    __syncthreads();
    const float d = rsqrtf(red[0] + red[1] + red[2] + red[3] + 1e-8f);

    for (int i = tid; i < 3456; i += 128) {
        const int ci = i / 27, tap = i - ci * 27;
        const uint32_t tv = f2tf32(wc[i] * d);
        const int lane = (co & 7) * 4 + (ci & 3);
        const int r = ((ci >> 2) & 1) * 2 + ((co >> 3) & 1);
        const int idx = ((tap * 16 + (ci >> 3)) * 8 + (co >> 4)) * 128 + lane * 4 + r;
        g_wA[idx] = tv;
    }
}

// ---------------------------------------------------------------------------
// conv: grid (4 ytiles, 32 z, 8 b), block 256 (8 warps, 2m x 4n).
// smem xs: ext tile [r = ez*360+ey*36+ex (1080)][ci-pair interleave (8)]
//   word = r*8 + (ci&3)*2 + (ci>>2)   -> B frag (ci=tig, tig+4) = LDS.64
// ---------------------------------------------------------------------------
__global__ __launch_bounds__(256, 1)
void conv_kernel(const float* __restrict__ x, const float* __restrict__ bias,
                 float* __restrict__ out) {
    __shared__ uint32_t xs[1080 * 8];  // 34.5 KB

    const int tid  = threadIdx.x;
    const int lane = tid & 31, wid = tid >> 5;
    const int wm = wid >> 2, wn = wid & 3;
    const int g = lane >> 2, tig = lane & 3;

    const int y0 = blockIdx.x * 8, z = blockIdx.y, b = blockIdx.z;

    float acc[4][8][4];
    #pragma unroll
    for (int mf = 0; mf < 4; mf++)
        #pragma unroll
        for (int nf = 0; nf < 8; nf++)
            #pragma unroll
            for (int r = 0; r < 4; r++) acc[mf][nf][r] = 0.f;

    // per-nf base row (spatial): r_read = rb + dz*360 + dy*36 + dx
    int rb[8];
    #pragma unroll
    for (int nf = 0; nf < 8; nf++) {
        const int n = wn * 64 + nf * 8 + g;
        rb[nf] = (n >> 5) * 36 + (n & 31);
    }

    const float* xb = x + (size_t)b * 128 * 32768;

    for (int chunk = 0; chunk < 16; chunk++) {
        __syncthreads();
        // ---- fill ext tile for ci8 = chunk*8 .. +7 ----
        {
            const float* src0 = xb + (size_t)chunk * 8 * 32768;
            for (int rr = tid; rr < 1080; rr += 256) {
                const int ex = rr % 36;
                const int t  = rr / 36;
                const int ey = t % 10, ez = t / 10;
                const int gx = ex - 1, gy = y0 + ey - 1, gz = z + ez - 1;
                const bool ok = (unsigned)gx < 32u && (unsigned)gy < 32u &&
                                (unsigned)gz < 32u;
                const float* src = src0 + gz * 1024 + gy * 32 + gx;
                uint32_t* dst = &xs[rr * 8];
                #pragma unroll
                for (int c = 0; c < 8; c++) {
                    const float v = ok ? src[c * 32768] : 0.f;
                    dst[(c & 3) * 2 + (c >> 2)] = f2tf32(v);
                }
            }
        }
        __syncthreads();

        // ---- compute: 27 taps x (ci8 k-block) ----
        const uint32_t* Ab = g_wA + (chunk * 8 + wm * 4) * 128 + lane * 4;
        #pragma unroll 3
        for (int tap = 0; tap < 27; tap++) {
            const int dz = tap / 9, r2 = tap % 9;
            const int dy = r2 / 3, dx = r2 % 3;
            const int tapw = (dz * 360 + dy * 36 + dx) * 8 + tig * 2;

            uint4 a[4];
            #pragma unroll
            for (int mf = 0; mf < 4; mf++)
                a[mf] = *(const uint4*)(Ab + (tap * 16 * 8 + mf) * 128);

            #pragma unroll
            for (int nf = 0; nf < 8; nf++) {
                const uint2 bv = *(const uint2*)&xs[rb[nf] * 8 + tapw];
                #pragma unroll
                for (int mf = 0; mf < 4; mf++)
                    mma8(acc[mf][nf], a[mf], bv.x, bv.y);
            }
        }
    }

    // ---- epilogue: +bias, lrelu(0.2), *sqrt2, clamp +-256 ----
    const float SQ2 = 1.41421356237309515f;
    #pragma unroll
    for (int mf = 0; mf < 4; mf++) {
        const int co = wm * 64 + mf * 16 + g;
        const float b0 = bias[co], b1 = bias[co + 8];
        float* o0 = out + (size_t)(b * 128 + co) * 32768 + z * 1024;
        float* o1 = o0 + (size_t)8 * 32768;
        #pragma unroll
        for (int nf = 0; nf < 8; nf++) {
            const int n = wn * 64 + nf * 8 + tig * 2;
            const int yy = y0 + (n >> 5), xx = n & 31;
            float v00 = acc[mf][nf][0] + b0, v01 = acc[mf][nf][1] + b0;
            float v10 = acc[mf][nf][2] + b1, v11 = acc[mf][nf][3] + b1;
            v00 = (v00 > 0.f) ? v00 : 0.2f * v00;
            v01 = (v01 > 0.f) ? v01 : 0.2f * v01;
            v10 = (v10 > 0.f) ? v10 : 0.2f * v10;
            v11 = (v11 > 0.f) ? v11 : 0.2f * v11;
            float2 p0, p1;
            p0.x = fminf(fmaxf(v00 * SQ2, -256.f), 256.f);
            p0.y = fminf(fmaxf(v01 * SQ2, -256.f), 256.f);
            p1.x = fminf(fmaxf(v10 * SQ2, -256.f), 256.f);
            p1.y = fminf(fmaxf(v11 * SQ2, -256.f), 256.f);
            *(float2*)(o0 + yy * 32 + xx) = p0;
            *(float2*)(o1 + yy * 32 + xx) = p1;
        }
    }
}

// ---------------------------------------------------------------------------
extern "C" void kernel_launch(void* const* d_in, const int* in_sizes, int n_in,
                              void* d_out, int out_size) {
    const float* x    = (const float*)d_in[0];
    const float* w    = (const float*)d_in[1];
    const float* bias = (const float*)d_in[2];
    float* out        = (float*)d_out;

    prep_kernel<<<128, 128>>>(w);
    dim3 grid(4, 32, 8);
    conv_kernel<<<grid, 256>>>(x, bias, out);
}